// round 1
// baseline (speedup 1.0000x reference)
#include <cuda_runtime.h>
#include <math.h>

// ---------------------------------------------------------------------------
// Static scratch (allocation-free per harness rules)
// ---------------------------------------------------------------------------
#define N2MAX 1536
#define G2MAX (8*N2MAX)          // 12288
#define U1MAX 15872              // actual <= 6000 + 9600 = 15600
#define G1MAX (8*U1MAX)          // 126976
#define U0MAX 160256             // actual <= 16000 + 8*15600 = 140800

__device__ float g_acc2[(N2MAX+1)*128];
__device__ float g_tg2[(size_t)G2MAX*128];
__device__ float g_accg2[((size_t)G2MAX+1)*128];
__device__ float g_x1[(size_t)U1MAX*128];
__device__ float g_acc1[((size_t)U1MAX+1)*128];
__device__ float g_t1[(size_t)G1MAX*64];
__device__ float g_accg1[((size_t)G1MAX+1)*64];
__device__ float g_x0[(size_t)U0MAX*64];
__device__ float g_acc0[((size_t)U0MAX+1)*128];
__device__ float g_stats[256];

// ---------------------------------------------------------------------------
// Generic gather/scatter tiled SGEMM:  C[om[r]] (+)= X[im[r]] @ W
//   im/om == nullptr -> identity indices.
//   64x64 tile, K-step 16, 256 threads, 4x4 per thread.
//   Scatter rows are unique per launch (scrap-row races are benign/unread).
// ---------------------------------------------------------------------------
__global__ void gemm_tap(const float* __restrict__ X, const float* __restrict__ W,
                         float* __restrict__ C,
                         const int* __restrict__ im, const int* __restrict__ om,
                         int M, int cin, int cout, int accumulate)
{
    __shared__ float As[16][65];
    __shared__ float Bs[16][65];
    __shared__ int gidx[64];
    __shared__ int sidx[64];

    const int row0 = blockIdx.y * 64;
    const int col0 = blockIdx.x * 64;
    const int tid  = threadIdx.x;

    if (tid < 64) {
        int r = row0 + tid;
        gidx[tid] = (r < M) ? (im ? im[r] : r) : -1;
        sidx[tid] = (r < M) ? (om ? om[r] : r) : -1;
    }
    __syncthreads();

    const int tr = tid >> 4;   // 0..15
    const int tc = tid & 15;   // 0..15

    float acc[4][4];
    #pragma unroll
    for (int i = 0; i < 4; i++)
        #pragma unroll
        for (int j = 0; j < 4; j++) acc[i][j] = 0.f;

    for (int k0 = 0; k0 < cin; k0 += 16) {
        // A tile: 16 consecutive threads read 16 consecutive k of one row
        #pragma unroll
        for (int l = 0; l < 4; l++) {
            int idx = tid + l * 256;       // 0..1023
            int m = idx >> 4;              // 0..63
            int k = idx & 15;              // 0..15
            int g = gidx[m];
            As[k][m] = (g >= 0) ? X[(size_t)g * cin + k0 + k] : 0.f;
        }
        // B tile: coalesced over cout
        #pragma unroll
        for (int l = 0; l < 4; l++) {
            int idx = tid + l * 256;
            int n = idx & 63;
            int k = idx >> 6;
            Bs[k][n] = W[(size_t)(k0 + k) * cout + col0 + n];
        }
        __syncthreads();

        #pragma unroll
        for (int k = 0; k < 16; k++) {
            float a[4], b[4];
            #pragma unroll
            for (int i = 0; i < 4; i++) a[i] = As[k][tr * 4 + i];
            #pragma unroll
            for (int j = 0; j < 4; j++) b[j] = Bs[k][tc * 4 + j];
            #pragma unroll
            for (int i = 0; i < 4; i++)
                #pragma unroll
                for (int j = 0; j < 4; j++)
                    acc[i][j] += a[i] * b[j];
        }
        __syncthreads();
    }

    #pragma unroll
    for (int i = 0; i < 4; i++) {
        int m = tr * 4 + i;
        int o = sidx[m];
        if (o < 0) continue;
        float* cp = C + (size_t)o * cout + col0 + tc * 4;
        #pragma unroll
        for (int j = 0; j < 4; j++) {
            if (accumulate) cp[j] += acc[i][j];
            else            cp[j] = acc[i][j];
        }
    }
}

// ---------------------------------------------------------------------------
// BatchNorm (training-mode batch stats) + ELU
// ---------------------------------------------------------------------------
__global__ void bn_stats(const float* __restrict__ X, int n, int c,
                         float* __restrict__ stats)
{
    int ch = threadIdx.x;                  // blockDim.x == c
    int r0 = blockIdx.x * 512;
    int rend = r0 + 512; if (rend > n) rend = n;
    float s = 0.f, sq = 0.f;
    for (int r = r0; r < rend; r++) {
        float v = X[(size_t)r * c + ch];
        s += v; sq += v * v;
    }
    atomicAdd(&stats[ch], s);
    atomicAdd(&stats[c + ch], sq);
}

__global__ void bn_apply(const float* __restrict__ X, float* __restrict__ Y,
                         const float* __restrict__ stats,
                         const float* __restrict__ gb, long long total, int n, int c)
{
    long long i = (long long)blockIdx.x * blockDim.x + threadIdx.x;
    if (i >= total) return;
    int ch = (int)(i % c);
    float inv_n = 1.f / (float)n;
    float mu  = stats[ch] * inv_n;
    float var = stats[c + ch] * inv_n - mu * mu;
    float v = gb[ch] * (X[i] - mu) * rsqrtf(var + 1e-5f) + gb[c + ch];
    Y[i] = (v > 0.f) ? v : expm1f(v);
}

// ---------------------------------------------------------------------------
// Sparse-add scatter helpers (indices unique within each launch)
// ---------------------------------------------------------------------------
__global__ void scatter_copy(const float* __restrict__ src, float* __restrict__ dst,
                             const int* __restrict__ idx, long long total, int c)
{
    long long i = (long long)blockIdx.x * blockDim.x + threadIdx.x;
    if (i >= total) return;
    int r = (int)(i / c), ch = (int)(i % c);
    dst[(size_t)idx[r] * c + ch] = src[i];
}

__global__ void scatter_add(const float* __restrict__ src, float* __restrict__ dst,
                            const int* __restrict__ idx, long long total, int c)
{
    long long i = (long long)blockIdx.x * blockDim.x + threadIdx.x;
    if (i >= total) return;
    int r = (int)(i / c), ch = (int)(i % c);
    dst[(size_t)idx[r] * c + ch] += src[i];
}

// ---------------------------------------------------------------------------
// Host-side orchestration
// ---------------------------------------------------------------------------
static void sconv3_launch(const float* X, const float* W, const int* m,
                          int n, int M, int cin, int cout, float* acc)
{
    for (int j = 0; j < 26; j++) {
        int k = (j < 13) ? j : j + 1;        // skip center tap 13
        dim3 grid(cout / 64, (M + 63) / 64);
        gemm_tap<<<grid, 256>>>(X, W + (size_t)k * cin * cout, acc,
                                m + (size_t)j * M, m + (size_t)(26 + j) * M,
                                M, cin, cout, 1);
    }
    dim3 grid(cout / 64, (n + 63) / 64);
    gemm_tap<<<grid, 256>>>(X, W + (size_t)13 * cin * cout, acc,
                            nullptr, nullptr, n, cin, cout, 1);
}

static void bn_elu_launch(const float* X, float* Y, const float* gb,
                          int n, int c, float* stats)
{
    cudaMemsetAsync(stats, 0, 2 * c * sizeof(float), 0);
    bn_stats<<<(n + 511) / 512, c>>>(X, n, c, stats);
    long long total = (long long)n * c;
    bn_apply<<<(unsigned)((total + 255) / 256), 256>>>(X, Y, stats, gb, total, n, c);
}

extern "C" void kernel_launch(void* const* d_in, const int* in_sizes, int n_in,
                              void* d_out, int out_size)
{
    const float* feats0 = (const float*)d_in[0];
    const float* feats1 = (const float*)d_in[1];
    const float* feats2 = (const float*)d_in[2];
    const float* w_out0 = (const float*)d_in[3];
    const float* w_out1 = (const float*)d_in[4];
    const float* w_out2 = (const float*)d_in[5];
    const float* wt2    = (const float*)d_in[6];
    const float* wu2    = (const float*)d_in[7];
    const float* wt1    = (const float*)d_in[8];
    const float* wu1    = (const float*)d_in[9];
    const float* bn_out0 = (const float*)d_in[10];
    const float* bn_out1 = (const float*)d_in[11];
    const float* bn_out2 = (const float*)d_in[12];
    const float* bn_up2a = (const float*)d_in[13];
    const float* bn_up2b = (const float*)d_in[14];
    const float* bn_up1a = (const float*)d_in[15];
    const float* bn_up1b = (const float*)d_in[16];
    const int* m_c2 = (const int*)d_in[19];
    const int* m_g2 = (const int*)d_in[20];
    const int* m_u1 = (const int*)d_in[21];
    const int* m_g1 = (const int*)d_in[22];
    const int* m_u0 = (const int*)d_in[23];
    const int* lat1_idx = (const int*)d_in[24];
    const int* up1_idx  = (const int*)d_in[25];
    const int* lat0_idx = (const int*)d_in[26];
    const int* up0_idx  = (const int*)d_in[27];

    const int N0 = in_sizes[0] / 64;
    const int N1 = in_sizes[1] / 128;
    const int N2 = in_sizes[2] / 256;
    const int U1 = in_sizes[17] / 128;
    const int U0 = in_sizes[18] / 64;
    const int Mc2 = in_sizes[19] / 52;
    const int Mg2 = in_sizes[20] / 52;
    const int Mu1 = in_sizes[21] / 52;
    const int Mg1 = in_sizes[22] / 52;
    const int Mu0 = in_sizes[23] / 52;
    const int G2 = 8 * N2;
    const int G1 = 8 * U1;

    float *acc2, *tg2, *accg2, *x1, *acc1, *t1, *accg1, *x0, *acc0, *stats;
    cudaGetSymbolAddress((void**)&acc2,  g_acc2);
    cudaGetSymbolAddress((void**)&tg2,   g_tg2);
    cudaGetSymbolAddress((void**)&accg2, g_accg2);
    cudaGetSymbolAddress((void**)&x1,    g_x1);
    cudaGetSymbolAddress((void**)&acc1,  g_acc1);
    cudaGetSymbolAddress((void**)&t1,    g_t1);
    cudaGetSymbolAddress((void**)&accg1, g_accg1);
    cudaGetSymbolAddress((void**)&x0,    g_x0);
    cudaGetSymbolAddress((void**)&acc0,  g_acc0);
    cudaGetSymbolAddress((void**)&stats, g_stats);

    float* out0 = (float*)d_out;                       // [U0,128]
    float* out1 = out0 + (size_t)U0 * 128;             // [U1,128]
    float* out2 = out1 + (size_t)U1 * 128;             // [N2,128]

    // ===== level 2: out2 = bn_elu(sconv3(feats2, w_out2, m_c2)) =====
    cudaMemsetAsync(acc2, 0, (size_t)(N2 + 1) * 128 * sizeof(float), 0);
    sconv3_launch(feats2, w_out2, m_c2, N2, Mc2, 256, 128, acc2);
    bn_elu_launch(acc2, out2, bn_out2, N2, 128, stats);

    // ===== up block 2: transpose conv (8 children) -> BN/ELU -> conv3 -> BN/ELU =====
    for (int o = 0; o < 8; o++) {
        dim3 grid(128 / 64, (N2 + 63) / 64);
        gemm_tap<<<grid, 256>>>(feats2, wt2 + (size_t)o * 256 * 128,
                                tg2 + (size_t)o * N2 * 128,
                                nullptr, nullptr, N2, 256, 128, 0);
    }
    bn_elu_launch(tg2, tg2, bn_up2a, G2, 128, stats);
    cudaMemsetAsync(accg2, 0, (size_t)(G2 + 1) * 128 * sizeof(float), 0);
    sconv3_launch(tg2, wu2, m_g2, G2, Mg2, 128, 128, accg2);
    bn_elu_launch(accg2, accg2, bn_up2b, G2, 128, stats);

    // ===== x1 = union add =====
    cudaMemsetAsync(x1, 0, (size_t)U1 * 128 * sizeof(float), 0);
    {
        long long t = (long long)N1 * 128;
        scatter_copy<<<(unsigned)((t + 255) / 256), 256>>>(feats1, x1, lat1_idx, t, 128);
        t = (long long)G2 * 128;
        scatter_add<<<(unsigned)((t + 255) / 256), 256>>>(accg2, x1, up1_idx, t, 128);
    }

    // ===== out1 =====
    cudaMemsetAsync(acc1, 0, (size_t)(U1 + 1) * 128 * sizeof(float), 0);
    sconv3_launch(x1, w_out1, m_u1, U1, Mu1, 128, 128, acc1);
    bn_elu_launch(acc1, out1, bn_out1, U1, 128, stats);

    // ===== up block 1 =====
    for (int o = 0; o < 8; o++) {
        dim3 grid(64 / 64, (U1 + 63) / 64);
        gemm_tap<<<grid, 256>>>(x1, wt1 + (size_t)o * 128 * 64,
                                t1 + (size_t)o * U1 * 64,
                                nullptr, nullptr, U1, 128, 64, 0);
    }
    bn_elu_launch(t1, t1, bn_up1a, G1, 64, stats);
    cudaMemsetAsync(accg1, 0, (size_t)(G1 + 1) * 64 * sizeof(float), 0);
    sconv3_launch(t1, wu1, m_g1, G1, Mg1, 64, 64, accg1);
    bn_elu_launch(accg1, accg1, bn_up1b, G1, 64, stats);

    // ===== x0 = union add =====
    cudaMemsetAsync(x0, 0, (size_t)U0 * 64 * sizeof(float), 0);
    {
        long long t = (long long)N0 * 64;
        scatter_copy<<<(unsigned)((t + 255) / 256), 256>>>(feats0, x0, lat0_idx, t, 64);
        t = (long long)G1 * 64;
        scatter_add<<<(unsigned)((t + 255) / 256), 256>>>(accg1, x0, up0_idx, t, 64);
    }

    // ===== out0 =====
    cudaMemsetAsync(acc0, 0, (size_t)(U0 + 1) * 128 * sizeof(float), 0);
    sconv3_launch(x0, w_out0, m_u0, U0, Mu0, 64, 128, acc0);
    bn_elu_launch(acc0, out0, bn_out0, U0, 128, stats);
}

// round 2
// speedup vs baseline: 4.7084x; 4.7084x over previous
#include <cuda_runtime.h>
#include <math.h>

// ---------------------------------------------------------------------------
// Static scratch (allocation-free per harness rules)
// ---------------------------------------------------------------------------
#define N2MAX 1536
#define G2MAX (8*N2MAX)          // 12288
#define U1MAX 15872              // actual <= 6000 + 9600 = 15600
#define G1MAX (8*U1MAX)          // 126976
#define U0MAX 160256             // actual <= 16000 + 8*15600 = 140800

__device__ float g_acc2[(N2MAX+1)*128];
__device__ float g_tg2[(size_t)G2MAX*128];
__device__ float g_accg2[((size_t)G2MAX+1)*128];
__device__ float g_x1[(size_t)U1MAX*128];
__device__ float g_acc1[((size_t)U1MAX+1)*128];
__device__ float g_t1[(size_t)G1MAX*64];
__device__ float g_accg1[((size_t)G1MAX+1)*64];
__device__ float g_x0[(size_t)U0MAX*64];
__device__ float g_acc0[((size_t)U0MAX+1)*128];
__device__ float g_stats[256];

// ---------------------------------------------------------------------------
// Batched tap conv:  for z in [0,26): C[om[z,r]] += X[im[z,r]] @ W[tap(z)]
//                    z == 26:         C[r]       += X[r]       @ W[13]
// One launch per sparse conv. grid = (cout/64, ceil(n/128), 27).
// 128x64 block tile, 256 threads, 8x4 per thread, K-step 16.
// Scatter via atomicAdd (cross-tap conflicts only; fp32 RED).
// ---------------------------------------------------------------------------
__global__ __launch_bounds__(256) void conv_taps(
    const float* __restrict__ X, const float* __restrict__ W27,
    float* __restrict__ C, const int* __restrict__ maps,
    int Mpad, int n, int cin, int cout)
{
    __shared__ float As[16][132];
    __shared__ float Bs[16][68];
    __shared__ int gidx[128];
    __shared__ int sidx[128];

    const int z    = blockIdx.z;
    const int Mz   = (z == 26) ? n : Mpad;
    const int row0 = blockIdx.y * 128;
    if (row0 >= Mz) return;

    const int tap  = (z == 26) ? 13 : ((z < 13) ? z : z + 1);
    const float* W = W27 + (size_t)tap * cin * cout;
    const int col0 = blockIdx.x * 64;
    const int tid  = threadIdx.x;
    const int scrap = n;

    int myvalid = 0;
    if (tid < 128) {
        int r = row0 + tid;
        int g = -1, s = -1;
        if (r < Mz) {
            if (z == 26) { g = r; s = r; }
            else {
                g = maps[(size_t)z * Mpad + r];
                s = maps[(size_t)(26 + z) * Mpad + r];
            }
        }
        gidx[tid] = g;
        sidx[tid] = s;
        myvalid = (s >= 0 && s != scrap);
    }
    // barrier + all-scrap (pure padding) early exit
    if (__syncthreads_count(myvalid) == 0) return;

    const int tr = tid >> 4;   // 0..15 -> rows tr*8 .. tr*8+7
    const int tc = tid & 15;   // cols tc*4 .. tc*4+3

    float acc[8][4];
    #pragma unroll
    for (int i = 0; i < 8; i++)
        #pragma unroll
        for (int j = 0; j < 4; j++) acc[i][j] = 0.f;

    for (int k0 = 0; k0 < cin; k0 += 16) {
        // A tile: 128 rows x 16 k (gathered)
        #pragma unroll
        for (int l = 0; l < 8; l++) {
            int idx = tid + l * 256;      // 0..2047
            int m = idx >> 4;             // 0..127
            int k = idx & 15;
            int g = gidx[m];
            As[k][m] = (g >= 0) ? X[(size_t)g * cin + k0 + k] : 0.f;
        }
        // B tile: 16 k x 64 cols (coalesced)
        #pragma unroll
        for (int l = 0; l < 4; l++) {
            int idx = tid + l * 256;
            int nn = idx & 63;
            int k = idx >> 6;
            Bs[k][nn] = W[(size_t)(k0 + k) * cout + col0 + nn];
        }
        __syncthreads();

        #pragma unroll
        for (int k = 0; k < 16; k++) {
            float a[8], b[4];
            #pragma unroll
            for (int i = 0; i < 8; i++) a[i] = As[k][tr * 8 + i];
            #pragma unroll
            for (int j = 0; j < 4; j++) b[j] = Bs[k][tc * 4 + j];
            #pragma unroll
            for (int i = 0; i < 8; i++)
                #pragma unroll
                for (int j = 0; j < 4; j++)
                    acc[i][j] += a[i] * b[j];
        }
        __syncthreads();
    }

    #pragma unroll
    for (int i = 0; i < 8; i++) {
        int o = sidx[tr * 8 + i];
        if (o < 0 || o == scrap) continue;
        float* cp = C + (size_t)o * cout + col0 + tc * 4;
        atomicAdd(cp + 0, acc[i][0]);
        atomicAdd(cp + 1, acc[i][1]);
        atomicAdd(cp + 2, acc[i][2]);
        atomicAdd(cp + 3, acc[i][3]);
    }
}

// ---------------------------------------------------------------------------
// Batched transpose conv: T[(z*n + r)] = X[r] @ Wt[z], z in [0,8)
// grid = (cout/64, ceil(n/128), 8); direct stores (disjoint outputs).
// ---------------------------------------------------------------------------
__global__ __launch_bounds__(256) void tconv8(
    const float* __restrict__ X, const float* __restrict__ W8,
    float* __restrict__ T, int n, int cin, int cout)
{
    __shared__ float As[16][132];
    __shared__ float Bs[16][68];

    const int z    = blockIdx.z;
    const int row0 = blockIdx.y * 128;
    if (row0 >= n) return;
    const float* W = W8 + (size_t)z * cin * cout;
    const int col0 = blockIdx.x * 64;
    const int tid  = threadIdx.x;

    const int tr = tid >> 4;
    const int tc = tid & 15;

    float acc[8][4];
    #pragma unroll
    for (int i = 0; i < 8; i++)
        #pragma unroll
        for (int j = 0; j < 4; j++) acc[i][j] = 0.f;

    for (int k0 = 0; k0 < cin; k0 += 16) {
        #pragma unroll
        for (int l = 0; l < 8; l++) {
            int idx = tid + l * 256;
            int m = idx >> 4;
            int k = idx & 15;
            int r = row0 + m;
            As[k][m] = (r < n) ? X[(size_t)r * cin + k0 + k] : 0.f;
        }
        #pragma unroll
        for (int l = 0; l < 4; l++) {
            int idx = tid + l * 256;
            int nn = idx & 63;
            int k = idx >> 6;
            Bs[k][nn] = W[(size_t)(k0 + k) * cout + col0 + nn];
        }
        __syncthreads();

        #pragma unroll
        for (int k = 0; k < 16; k++) {
            float a[8], b[4];
            #pragma unroll
            for (int i = 0; i < 8; i++) a[i] = As[k][tr * 8 + i];
            #pragma unroll
            for (int j = 0; j < 4; j++) b[j] = Bs[k][tc * 4 + j];
            #pragma unroll
            for (int i = 0; i < 8; i++)
                #pragma unroll
                for (int j = 0; j < 4; j++)
                    acc[i][j] += a[i] * b[j];
        }
        __syncthreads();
    }

    #pragma unroll
    for (int i = 0; i < 8; i++) {
        int r = row0 + tr * 8 + i;
        if (r >= n) continue;
        float* tp = T + ((size_t)z * n + r) * cout + col0 + tc * 4;
        tp[0] = acc[i][0];
        tp[1] = acc[i][1];
        tp[2] = acc[i][2];
        tp[3] = acc[i][3];
    }
}

// ---------------------------------------------------------------------------
// BatchNorm (training-mode batch stats) + ELU
// ---------------------------------------------------------------------------
__global__ void bn_stats(const float* __restrict__ X, int n, int c,
                         float* __restrict__ stats)
{
    int ch = threadIdx.x;                  // blockDim.x == c
    int r0 = blockIdx.x * 128;
    int rend = r0 + 128; if (rend > n) rend = n;
    float s = 0.f, sq = 0.f;
    for (int r = r0; r < rend; r++) {
        float v = X[(size_t)r * c + ch];
        s += v; sq += v * v;
    }
    atomicAdd(&stats[ch], s);
    atomicAdd(&stats[c + ch], sq);
}

__global__ void bn_apply(const float* __restrict__ X, float* __restrict__ Y,
                         const float* __restrict__ stats,
                         const float* __restrict__ gb, long long total, int n, int c)
{
    long long i = (long long)blockIdx.x * blockDim.x + threadIdx.x;
    if (i >= total) return;
    int ch = (int)(i % c);
    float inv_n = 1.f / (float)n;
    float mu  = stats[ch] * inv_n;
    float var = stats[c + ch] * inv_n - mu * mu;
    float v = gb[ch] * (X[i] - mu) * rsqrtf(var + 1e-5f) + gb[c + ch];
    Y[i] = (v > 0.f) ? v : expm1f(v);
}

// ---------------------------------------------------------------------------
// Sparse-add scatter helpers (indices unique within each launch)
// ---------------------------------------------------------------------------
__global__ void scatter_copy(const float* __restrict__ src, float* __restrict__ dst,
                             const int* __restrict__ idx, long long total, int c)
{
    long long i = (long long)blockIdx.x * blockDim.x + threadIdx.x;
    if (i >= total) return;
    int r = (int)(i / c), ch = (int)(i % c);
    dst[(size_t)idx[r] * c + ch] = src[i];
}

__global__ void scatter_add(const float* __restrict__ src, float* __restrict__ dst,
                            const int* __restrict__ idx, long long total, int c)
{
    long long i = (long long)blockIdx.x * blockDim.x + threadIdx.x;
    if (i >= total) return;
    int r = (int)(i / c), ch = (int)(i % c);
    dst[(size_t)idx[r] * c + ch] += src[i];
}

// ---------------------------------------------------------------------------
// Host-side orchestration
// ---------------------------------------------------------------------------
static void sconv3_launch(const float* X, const float* W, const int* m,
                          int n, int Mpad, int cin, int cout, float* acc)
{
    dim3 grid(cout / 64, (n + 127) / 128, 27);
    conv_taps<<<grid, 256>>>(X, W, acc, m, Mpad, n, cin, cout);
}

static void bn_elu_launch(const float* X, float* Y, const float* gb,
                          int n, int c, float* stats)
{
    cudaMemsetAsync(stats, 0, 2 * c * sizeof(float), 0);
    bn_stats<<<(n + 127) / 128, c>>>(X, n, c, stats);
    long long total = (long long)n * c;
    bn_apply<<<(unsigned)((total + 255) / 256), 256>>>(X, Y, stats, gb, total, n, c);
}

extern "C" void kernel_launch(void* const* d_in, const int* in_sizes, int n_in,
                              void* d_out, int out_size)
{
    const float* feats0 = (const float*)d_in[0];
    const float* feats1 = (const float*)d_in[1];
    const float* feats2 = (const float*)d_in[2];
    const float* w_out0 = (const float*)d_in[3];
    const float* w_out1 = (const float*)d_in[4];
    const float* w_out2 = (const float*)d_in[5];
    const float* wt2    = (const float*)d_in[6];
    const float* wu2    = (const float*)d_in[7];
    const float* wt1    = (const float*)d_in[8];
    const float* wu1    = (const float*)d_in[9];
    const float* bn_out0 = (const float*)d_in[10];
    const float* bn_out1 = (const float*)d_in[11];
    const float* bn_out2 = (const float*)d_in[12];
    const float* bn_up2a = (const float*)d_in[13];
    const float* bn_up2b = (const float*)d_in[14];
    const float* bn_up1a = (const float*)d_in[15];
    const float* bn_up1b = (const float*)d_in[16];
    const int* m_c2 = (const int*)d_in[19];
    const int* m_g2 = (const int*)d_in[20];
    const int* m_u1 = (const int*)d_in[21];
    const int* m_g1 = (const int*)d_in[22];
    const int* m_u0 = (const int*)d_in[23];
    const int* lat1_idx = (const int*)d_in[24];
    const int* up1_idx  = (const int*)d_in[25];
    const int* lat0_idx = (const int*)d_in[26];
    const int* up0_idx  = (const int*)d_in[27];

    const int N0 = in_sizes[0] / 64;
    const int N1 = in_sizes[1] / 128;
    const int N2 = in_sizes[2] / 256;
    const int U1 = in_sizes[17] / 128;
    const int U0 = in_sizes[18] / 64;
    const int Mc2 = in_sizes[19] / 52;
    const int Mg2 = in_sizes[20] / 52;
    const int Mu1 = in_sizes[21] / 52;
    const int Mg1 = in_sizes[22] / 52;
    const int Mu0 = in_sizes[23] / 52;
    const int G2 = 8 * N2;
    const int G1 = 8 * U1;

    float *acc2, *tg2, *accg2, *x1, *acc1, *t1, *accg1, *x0, *acc0, *stats;
    cudaGetSymbolAddress((void**)&acc2,  g_acc2);
    cudaGetSymbolAddress((void**)&tg2,   g_tg2);
    cudaGetSymbolAddress((void**)&accg2, g_accg2);
    cudaGetSymbolAddress((void**)&x1,    g_x1);
    cudaGetSymbolAddress((void**)&acc1,  g_acc1);
    cudaGetSymbolAddress((void**)&t1,    g_t1);
    cudaGetSymbolAddress((void**)&accg1, g_accg1);
    cudaGetSymbolAddress((void**)&x0,    g_x0);
    cudaGetSymbolAddress((void**)&acc0,  g_acc0);
    cudaGetSymbolAddress((void**)&stats, g_stats);

    float* out0 = (float*)d_out;                       // [U0,128]
    float* out1 = out0 + (size_t)U0 * 128;             // [U1,128]
    float* out2 = out1 + (size_t)U1 * 128;             // [N2,128]

    // ===== level 2: out2 = bn_elu(sconv3(feats2, w_out2, m_c2)) =====
    cudaMemsetAsync(acc2, 0, (size_t)(N2 + 1) * 128 * sizeof(float), 0);
    sconv3_launch(feats2, w_out2, m_c2, N2, Mc2, 256, 128, acc2);
    bn_elu_launch(acc2, out2, bn_out2, N2, 128, stats);

    // ===== up block 2: tconv (8 children) -> BN/ELU -> conv3 -> BN/ELU =====
    {
        dim3 grid(128 / 64, (N2 + 127) / 128, 8);
        tconv8<<<grid, 256>>>(feats2, wt2, tg2, N2, 256, 128);
    }
    bn_elu_launch(tg2, tg2, bn_up2a, G2, 128, stats);
    cudaMemsetAsync(accg2, 0, (size_t)(G2 + 1) * 128 * sizeof(float), 0);
    sconv3_launch(tg2, wu2, m_g2, G2, Mg2, 128, 128, accg2);
    bn_elu_launch(accg2, accg2, bn_up2b, G2, 128, stats);

    // ===== x1 = union add =====
    cudaMemsetAsync(x1, 0, (size_t)U1 * 128 * sizeof(float), 0);
    {
        long long t = (long long)N1 * 128;
        scatter_copy<<<(unsigned)((t + 255) / 256), 256>>>(feats1, x1, lat1_idx, t, 128);
        t = (long long)G2 * 128;
        scatter_add<<<(unsigned)((t + 255) / 256), 256>>>(accg2, x1, up1_idx, t, 128);
    }

    // ===== out1 =====
    cudaMemsetAsync(acc1, 0, (size_t)(U1 + 1) * 128 * sizeof(float), 0);
    sconv3_launch(x1, w_out1, m_u1, U1, Mu1, 128, 128, acc1);
    bn_elu_launch(acc1, out1, bn_out1, U1, 128, stats);

    // ===== up block 1 =====
    {
        dim3 grid(64 / 64, (U1 + 127) / 128, 8);
        tconv8<<<grid, 256>>>(x1, wt1, t1, U1, 128, 64);
    }
    bn_elu_launch(t1, t1, bn_up1a, G1, 64, stats);
    cudaMemsetAsync(accg1, 0, (size_t)(G1 + 1) * 64 * sizeof(float), 0);
    sconv3_launch(t1, wu1, m_g1, G1, Mg1, 64, 64, accg1);
    bn_elu_launch(accg1, accg1, bn_up1b, G1, 64, stats);

    // ===== x0 = union add =====
    cudaMemsetAsync(x0, 0, (size_t)U0 * 64 * sizeof(float), 0);
    {
        long long t = (long long)N0 * 64;
        scatter_copy<<<(unsigned)((t + 255) / 256), 256>>>(feats0, x0, lat0_idx, t, 64);
        t = (long long)G1 * 64;
        scatter_add<<<(unsigned)((t + 255) / 256), 256>>>(accg1, x0, up0_idx, t, 64);
    }

    // ===== out0 =====
    cudaMemsetAsync(acc0, 0, (size_t)(U0 + 1) * 128 * sizeof(float), 0);
    sconv3_launch(x0, w_out0, m_u0, U0, Mu0, 64, 128, acc0);
    bn_elu_launch(acc0, out0, bn_out0, U0, 128, stats);
}

// round 3
// speedup vs baseline: 8.6111x; 1.8289x over previous
#include <cuda_runtime.h>
#include <math.h>

// ---------------------------------------------------------------------------
// Static scratch (allocation-free per harness rules)
// ---------------------------------------------------------------------------
#define N2MAX 1536
#define G2MAX (8*N2MAX)
#define U1MAX 15872
#define G1MAX (8*U1MAX)
#define U0MAX 160256

__device__ float g_acc2[(N2MAX+1)*128];
__device__ float g_tg2[(size_t)G2MAX*128];
__device__ float g_accg2[((size_t)G2MAX+1)*128];
__device__ float g_x1[(size_t)U1MAX*128];
__device__ float g_acc1[((size_t)U1MAX+1)*128];
__device__ float g_t1[(size_t)G1MAX*64];
__device__ float g_accg1[((size_t)G1MAX+1)*64];
__device__ float g_x0[(size_t)U0MAX*64];
__device__ float g_acc0[((size_t)U0MAX+1)*128];
__device__ float g_stats[256];

__device__ __forceinline__ unsigned f2tf32(float f) {
    unsigned r;
    asm("cvt.rna.tf32.f32 %0, %1;" : "=r"(r) : "f"(f));
    return r;
}

__device__ __forceinline__ void mma_tf32(float& c0, float& c1, float& c2, float& c3,
                                         unsigned a0, unsigned a1, unsigned a2, unsigned a3,
                                         unsigned b0, unsigned b1)
{
    asm volatile("mma.sync.aligned.m16n8k8.row.col.f32.tf32.tf32.f32 "
                 "{%0,%1,%2,%3},{%4,%5,%6,%7},{%8,%9},{%0,%1,%2,%3};"
                 : "+f"(c0), "+f"(c1), "+f"(c2), "+f"(c3)
                 : "r"(a0), "r"(a1), "r"(a2), "r"(a3), "r"(b0), "r"(b1));
}

// ---------------------------------------------------------------------------
// Core tf32 MMA tile: 128(m) x 64(n) block tile, 256 threads.
// Warps: 4 (m) x 2 (n); warp tile 32x32; K-step 16 (two k=8 mma slices).
// As[m][k] (pad 17), Bs[n][k] (pad 17), both tf32 bits.
// ---------------------------------------------------------------------------
#define PAD 17

struct MmaAcc { float c[2][4][4]; };

__device__ __forceinline__ void mma_tile_step(const unsigned (*As)[PAD],
                                              const unsigned (*Bs)[PAD],
                                              int wm, int wn, int lane, MmaAcc& A)
{
    const int qr = lane >> 2;   // 0..7
    const int qc = lane & 3;    // 0..3
    #pragma unroll
    for (int kt = 0; kt < 2; kt++) {
        const int kb = kt * 8;
        unsigned a[2][4];
        #pragma unroll
        for (int mi = 0; mi < 2; mi++) {
            const int rb = wm + mi * 16 + qr;
            a[mi][0] = As[rb    ][kb + qc];
            a[mi][1] = As[rb + 8][kb + qc];
            a[mi][2] = As[rb    ][kb + qc + 4];
            a[mi][3] = As[rb + 8][kb + qc + 4];
        }
        unsigned b[4][2];
        #pragma unroll
        for (int ni = 0; ni < 4; ni++) {
            const int nb = wn + ni * 8 + qr;
            b[ni][0] = Bs[nb][kb + qc];
            b[ni][1] = Bs[nb][kb + qc + 4];
        }
        #pragma unroll
        for (int mi = 0; mi < 2; mi++)
            #pragma unroll
            for (int ni = 0; ni < 4; ni++)
                mma_tf32(A.c[mi][ni][0], A.c[mi][ni][1], A.c[mi][ni][2], A.c[mi][ni][3],
                         a[mi][0], a[mi][1], a[mi][2], a[mi][3], b[ni][0], b[ni][1]);
    }
}

// ---------------------------------------------------------------------------
// Batched tap conv (tf32 MMA): z in [0,26): C[om[z,r]] += X[im[z,r]] @ W[tap(z)]
//                              z == 26:     C[r]       += X[r]       @ W[13]
// grid = (cout/64, ceil(n/128), 27), scatter via atomicAdd.
// ---------------------------------------------------------------------------
__global__ __launch_bounds__(256) void conv_taps(
    const float* __restrict__ X, const float* __restrict__ W27,
    float* __restrict__ C, const int* __restrict__ maps,
    int Mpad, int n, int cin, int cout)
{
    __shared__ unsigned As[128][PAD];
    __shared__ unsigned Bs[64][PAD];
    __shared__ int gidx[128];
    __shared__ int sidx[128];

    const int z    = blockIdx.z;
    const int Mz   = (z == 26) ? n : Mpad;
    const int row0 = blockIdx.y * 128;
    if (row0 >= Mz) return;

    const int tap  = (z == 26) ? 13 : ((z < 13) ? z : z + 1);
    const float* W = W27 + (size_t)tap * cin * cout;
    const int col0 = blockIdx.x * 64;
    const int tid  = threadIdx.x;
    const int scrap = n;

    int myvalid = 0;
    if (tid < 128) {
        int r = row0 + tid;
        int g = -1, s = -1;
        if (r < Mz) {
            if (z == 26) { g = r; s = r; }
            else {
                g = maps[(size_t)z * Mpad + r];
                s = maps[(size_t)(26 + z) * Mpad + r];
            }
        }
        gidx[tid] = g;
        sidx[tid] = s;
        myvalid = (s >= 0 && s != scrap);
    }
    if (__syncthreads_count(myvalid) == 0) return;

    const int lane = tid & 31;
    const int warp = tid >> 5;
    const int wm = (warp & 3) * 32;
    const int wn = (warp >> 2) * 32;

    MmaAcc A;
    #pragma unroll
    for (int mi = 0; mi < 2; mi++)
        #pragma unroll
        for (int ni = 0; ni < 4; ni++)
            #pragma unroll
            for (int j = 0; j < 4; j++) A.c[mi][ni][j] = 0.f;

    for (int k0 = 0; k0 < cin; k0 += 16) {
        // A tile: 128 rows x 16 k, gathered, float4 loads
        #pragma unroll
        for (int l = 0; l < 2; l++) {
            int idx = tid + l * 256;       // 0..511
            int m = idx >> 2;              // 0..127
            int q = idx & 3;               // float4 within 16
            int g = gidx[m];
            float4 v = make_float4(0.f, 0.f, 0.f, 0.f);
            if (g >= 0)
                v = *(const float4*)(X + (size_t)g * cin + k0 + q * 4);
            As[m][q*4+0] = f2tf32(v.x);
            As[m][q*4+1] = f2tf32(v.y);
            As[m][q*4+2] = f2tf32(v.z);
            As[m][q*4+3] = f2tf32(v.w);
        }
        // B tile: W[k][col0+n] -> Bs[n][k] (coalesced read, transposed store)
        #pragma unroll
        for (int l = 0; l < 4; l++) {
            int idx = tid + l * 256;
            int nn = idx & 63;
            int k = idx >> 6;
            Bs[nn][k] = f2tf32(W[(size_t)(k0 + k) * cout + col0 + nn]);
        }
        __syncthreads();
        mma_tile_step(As, Bs, wm, wn, lane, A);
        __syncthreads();
    }

    const int qr = lane >> 2, qc = lane & 3;
    #pragma unroll
    for (int mi = 0; mi < 2; mi++) {
        #pragma unroll
        for (int half = 0; half < 2; half++) {
            int lr = wm + mi * 16 + qr + half * 8;
            int o = sidx[lr];
            if (o < 0 || o == scrap) continue;
            float* cp = C + (size_t)o * cout + col0 + wn + qc * 2;
            #pragma unroll
            for (int ni = 0; ni < 4; ni++) {
                atomicAdd(cp + ni * 8,     A.c[mi][ni][half * 2 + 0]);
                atomicAdd(cp + ni * 8 + 1, A.c[mi][ni][half * 2 + 1]);
            }
        }
    }
}

// ---------------------------------------------------------------------------
// Batched transpose conv (tf32 MMA): T[z*n + r] = X[r] @ Wt[z], z in [0,8)
// ---------------------------------------------------------------------------
__global__ __launch_bounds__(256) void tconv8(
    const float* __restrict__ X, const float* __restrict__ W8,
    float* __restrict__ T, int n, int cin, int cout)
{
    __shared__ unsigned As[128][PAD];
    __shared__ unsigned Bs[64][PAD];

    const int z    = blockIdx.z;
    const int row0 = blockIdx.y * 128;
    if (row0 >= n) return;
    const float* W = W8 + (size_t)z * cin * cout;
    const int col0 = blockIdx.x * 64;
    const int tid  = threadIdx.x;

    const int lane = tid & 31;
    const int warp = tid >> 5;
    const int wm = (warp & 3) * 32;
    const int wn = (warp >> 2) * 32;

    MmaAcc A;
    #pragma unroll
    for (int mi = 0; mi < 2; mi++)
        #pragma unroll
        for (int ni = 0; ni < 4; ni++)
            #pragma unroll
            for (int j = 0; j < 4; j++) A.c[mi][ni][j] = 0.f;

    for (int k0 = 0; k0 < cin; k0 += 16) {
        #pragma unroll
        for (int l = 0; l < 2; l++) {
            int idx = tid + l * 256;
            int m = idx >> 2;
            int q = idx & 3;
            int r = row0 + m;
            float4 v = make_float4(0.f, 0.f, 0.f, 0.f);
            if (r < n)
                v = *(const float4*)(X + (size_t)r * cin + k0 + q * 4);
            As[m][q*4+0] = f2tf32(v.x);
            As[m][q*4+1] = f2tf32(v.y);
            As[m][q*4+2] = f2tf32(v.z);
            As[m][q*4+3] = f2tf32(v.w);
        }
        #pragma unroll
        for (int l = 0; l < 4; l++) {
            int idx = tid + l * 256;
            int nn = idx & 63;
            int k = idx >> 6;
            Bs[nn][k] = f2tf32(W[(size_t)(k0 + k) * cout + col0 + nn]);
        }
        __syncthreads();
        mma_tile_step(As, Bs, wm, wn, lane, A);
        __syncthreads();
    }

    const int qr = lane >> 2, qc = lane & 3;
    #pragma unroll
    for (int mi = 0; mi < 2; mi++) {
        #pragma unroll
        for (int half = 0; half < 2; half++) {
            int lr = wm + mi * 16 + qr + half * 8;
            int r = row0 + lr;
            if (r >= n) continue;
            float* tp = T + ((size_t)z * n + r) * cout + col0 + wn + qc * 2;
            #pragma unroll
            for (int ni = 0; ni < 4; ni++) {
                tp[ni * 8]     = A.c[mi][ni][half * 2 + 0];
                tp[ni * 8 + 1] = A.c[mi][ni][half * 2 + 1];
            }
        }
    }
}

// ---------------------------------------------------------------------------
// BatchNorm (training-mode batch stats) + ELU
// ---------------------------------------------------------------------------
__global__ void bn_stats(const float* __restrict__ X, int n, int c,
                         float* __restrict__ stats)
{
    int ch = threadIdx.x;
    int r0 = blockIdx.x * 128;
    int rend = r0 + 128; if (rend > n) rend = n;
    float s = 0.f, sq = 0.f;
    for (int r = r0; r < rend; r++) {
        float v = X[(size_t)r * c + ch];
        s += v; sq += v * v;
    }
    atomicAdd(&stats[ch], s);
    atomicAdd(&stats[c + ch], sq);
}

__global__ void bn_apply(const float* __restrict__ X, float* __restrict__ Y,
                         const float* __restrict__ stats,
                         const float* __restrict__ gb, long long total, int n, int c)
{
    long long i = (long long)blockIdx.x * blockDim.x + threadIdx.x;
    if (i >= total) return;
    int ch = (int)(i % c);
    float inv_n = 1.f / (float)n;
    float mu  = stats[ch] * inv_n;
    float var = stats[c + ch] * inv_n - mu * mu;
    float v = gb[ch] * (X[i] - mu) * rsqrtf(var + 1e-5f) + gb[c + ch];
    Y[i] = (v > 0.f) ? v : expm1f(v);
}

// ---------------------------------------------------------------------------
// Sparse-add scatter helpers
// ---------------------------------------------------------------------------
__global__ void scatter_copy(const float* __restrict__ src, float* __restrict__ dst,
                             const int* __restrict__ idx, long long total, int c)
{
    long long i = (long long)blockIdx.x * blockDim.x + threadIdx.x;
    if (i >= total) return;
    int r = (int)(i / c), ch = (int)(i % c);
    dst[(size_t)idx[r] * c + ch] = src[i];
}

__global__ void scatter_add(const float* __restrict__ src, float* __restrict__ dst,
                            const int* __restrict__ idx, long long total, int c)
{
    long long i = (long long)blockIdx.x * blockDim.x + threadIdx.x;
    if (i >= total) return;
    int r = (int)(i / c), ch = (int)(i % c);
    dst[(size_t)idx[r] * c + ch] += src[i];
}

// ---------------------------------------------------------------------------
// Host-side orchestration
// ---------------------------------------------------------------------------
static void sconv3_launch(const float* X, const float* W, const int* m,
                          int n, int Mpad, int cin, int cout, float* acc)
{
    dim3 grid(cout / 64, (n + 127) / 128, 27);
    conv_taps<<<grid, 256>>>(X, W, acc, m, Mpad, n, cin, cout);
}

static void bn_elu_launch(const float* X, float* Y, const float* gb,
                          int n, int c, float* stats)
{
    cudaMemsetAsync(stats, 0, 2 * c * sizeof(float), 0);
    bn_stats<<<(n + 127) / 128, c>>>(X, n, c, stats);
    long long total = (long long)n * c;
    bn_apply<<<(unsigned)((total + 255) / 256), 256>>>(X, Y, stats, gb, total, n, c);
}

extern "C" void kernel_launch(void* const* d_in, const int* in_sizes, int n_in,
                              void* d_out, int out_size)
{
    const float* feats0 = (const float*)d_in[0];
    const float* feats1 = (const float*)d_in[1];
    const float* feats2 = (const float*)d_in[2];
    const float* w_out0 = (const float*)d_in[3];
    const float* w_out1 = (const float*)d_in[4];
    const float* w_out2 = (const float*)d_in[5];
    const float* wt2    = (const float*)d_in[6];
    const float* wu2    = (const float*)d_in[7];
    const float* wt1    = (const float*)d_in[8];
    const float* wu1    = (const float*)d_in[9];
    const float* bn_out0 = (const float*)d_in[10];
    const float* bn_out1 = (const float*)d_in[11];
    const float* bn_out2 = (const float*)d_in[12];
    const float* bn_up2a = (const float*)d_in[13];
    const float* bn_up2b = (const float*)d_in[14];
    const float* bn_up1a = (const float*)d_in[15];
    const float* bn_up1b = (const float*)d_in[16];
    const int* m_c2 = (const int*)d_in[19];
    const int* m_g2 = (const int*)d_in[20];
    const int* m_u1 = (const int*)d_in[21];
    const int* m_g1 = (const int*)d_in[22];
    const int* m_u0 = (const int*)d_in[23];
    const int* lat1_idx = (const int*)d_in[24];
    const int* up1_idx  = (const int*)d_in[25];
    const int* lat0_idx = (const int*)d_in[26];
    const int* up0_idx  = (const int*)d_in[27];

    const int N0 = in_sizes[0] / 64;
    const int N1 = in_sizes[1] / 128;
    const int N2 = in_sizes[2] / 256;
    const int U1 = in_sizes[17] / 128;
    const int U0 = in_sizes[18] / 64;
    const int Mc2 = in_sizes[19] / 52;
    const int Mg2 = in_sizes[20] / 52;
    const int Mu1 = in_sizes[21] / 52;
    const int Mg1 = in_sizes[22] / 52;
    const int Mu0 = in_sizes[23] / 52;
    const int G2 = 8 * N2;
    const int G1 = 8 * U1;

    float *acc2, *tg2, *accg2, *x1, *acc1, *t1, *accg1, *x0, *acc0, *stats;
    cudaGetSymbolAddress((void**)&acc2,  g_acc2);
    cudaGetSymbolAddress((void**)&tg2,   g_tg2);
    cudaGetSymbolAddress((void**)&accg2, g_accg2);
    cudaGetSymbolAddress((void**)&x1,    g_x1);
    cudaGetSymbolAddress((void**)&acc1,  g_acc1);
    cudaGetSymbolAddress((void**)&t1,    g_t1);
    cudaGetSymbolAddress((void**)&accg1, g_accg1);
    cudaGetSymbolAddress((void**)&x0,    g_x0);
    cudaGetSymbolAddress((void**)&acc0,  g_acc0);
    cudaGetSymbolAddress((void**)&stats, g_stats);

    float* out0 = (float*)d_out;
    float* out1 = out0 + (size_t)U0 * 128;
    float* out2 = out1 + (size_t)U1 * 128;

    // ===== level 2 =====
    cudaMemsetAsync(acc2, 0, (size_t)(N2 + 1) * 128 * sizeof(float), 0);
    sconv3_launch(feats2, w_out2, m_c2, N2, Mc2, 256, 128, acc2);
    bn_elu_launch(acc2, out2, bn_out2, N2, 128, stats);

    // ===== up block 2 =====
    {
        dim3 grid(128 / 64, (N2 + 127) / 128, 8);
        tconv8<<<grid, 256>>>(feats2, wt2, tg2, N2, 256, 128);
    }
    bn_elu_launch(tg2, tg2, bn_up2a, G2, 128, stats);
    cudaMemsetAsync(accg2, 0, (size_t)(G2 + 1) * 128 * sizeof(float), 0);
    sconv3_launch(tg2, wu2, m_g2, G2, Mg2, 128, 128, accg2);
    bn_elu_launch(accg2, accg2, bn_up2b, G2, 128, stats);

    // ===== x1 = union add =====
    cudaMemsetAsync(x1, 0, (size_t)U1 * 128 * sizeof(float), 0);
    {
        long long t = (long long)N1 * 128;
        scatter_copy<<<(unsigned)((t + 255) / 256), 256>>>(feats1, x1, lat1_idx, t, 128);
        t = (long long)G2 * 128;
        scatter_add<<<(unsigned)((t + 255) / 256), 256>>>(accg2, x1, up1_idx, t, 128);
    }

    // ===== out1 =====
    cudaMemsetAsync(acc1, 0, (size_t)(U1 + 1) * 128 * sizeof(float), 0);
    sconv3_launch(x1, w_out1, m_u1, U1, Mu1, 128, 128, acc1);
    bn_elu_launch(acc1, out1, bn_out1, U1, 128, stats);

    // ===== up block 1 =====
    {
        dim3 grid(64 / 64, (U1 + 127) / 128, 8);
        tconv8<<<grid, 256>>>(x1, wt1, t1, U1, 128, 64);
    }
    bn_elu_launch(t1, t1, bn_up1a, G1, 64, stats);
    cudaMemsetAsync(accg1, 0, (size_t)(G1 + 1) * 64 * sizeof(float), 0);
    sconv3_launch(t1, wu1, m_g1, G1, Mg1, 64, 64, accg1);
    bn_elu_launch(accg1, accg1, bn_up1b, G1, 64, stats);

    // ===== x0 = union add =====
    cudaMemsetAsync(x0, 0, (size_t)U0 * 64 * sizeof(float), 0);
    {
        long long t = (long long)N0 * 64;
        scatter_copy<<<(unsigned)((t + 255) / 256), 256>>>(feats0, x0, lat0_idx, t, 64);
        t = (long long)G1 * 64;
        scatter_add<<<(unsigned)((t + 255) / 256), 256>>>(accg1, x0, up0_idx, t, 64);
    }

    // ===== out0 =====
    cudaMemsetAsync(acc0, 0, (size_t)(U0 + 1) * 128 * sizeof(float), 0);
    sconv3_launch(x0, w_out0, m_u0, U0, Mu0, 64, 128, acc0);
    bn_elu_launch(acc0, out0, bn_out0, U0, 128, stats);
}

// round 4
// speedup vs baseline: 8.6115x; 1.0000x over previous
#include <cuda_runtime.h>
#include <math.h>

// ---------------------------------------------------------------------------
// Static scratch (allocation-free per harness rules)
// ---------------------------------------------------------------------------
#define N2MAX 1536
#define G2MAX (8*N2MAX)
#define U1MAX 15872
#define G1MAX (8*U1MAX)
#define U0MAX 160256

__device__ float g_acc2[(N2MAX+1)*128];
__device__ float g_tg2[(size_t)G2MAX*128];
__device__ float g_accg2[((size_t)G2MAX+1)*128];
__device__ float g_x1[(size_t)U1MAX*128];
__device__ float g_acc1[((size_t)U1MAX+1)*128];
__device__ float g_t1[(size_t)G1MAX*64];
__device__ float g_accg1[((size_t)G1MAX+1)*64];
__device__ float g_x0[(size_t)U0MAX*64];
__device__ float g_acc0[((size_t)U0MAX+1)*128];
__device__ float g_stats[256];

__device__ __forceinline__ unsigned f2tf32(float f) {
    unsigned r;
    asm("cvt.rna.tf32.f32 %0, %1;" : "=r"(r) : "f"(f));
    return r;
}

__device__ __forceinline__ void mma_tf32(float& c0, float& c1, float& c2, float& c3,
                                         unsigned a0, unsigned a1, unsigned a2, unsigned a3,
                                         unsigned b0, unsigned b1)
{
    asm volatile("mma.sync.aligned.m16n8k8.row.col.f32.tf32.tf32.f32 "
                 "{%0,%1,%2,%3},{%4,%5,%6,%7},{%8,%9},{%0,%1,%2,%3};"
                 : "+f"(c0), "+f"(c1), "+f"(c2), "+f"(c3)
                 : "r"(a0), "r"(a1), "r"(a2), "r"(a3), "r"(b0), "r"(b1));
}

__device__ __forceinline__ void red_add_v4(float* p, float4 v) {
    asm volatile("red.global.add.v4.f32 [%0], {%1,%2,%3,%4};"
                 :: "l"(p), "f"(v.x), "f"(v.y), "f"(v.z), "f"(v.w) : "memory");
}

// ---------------------------------------------------------------------------
// Core tf32 MMA tile: 128(m) x 64(n) block tile, 256 threads.
// Warps: 4 (m) x 2 (n); warp tile 32x32; K-step 16 (two k=8 mma slices).
// ---------------------------------------------------------------------------
#define PAD 17
#define CPAD 36   // staging row stride: 16B-aligned float4, conflict-free

struct MmaAcc { float c[2][4][4]; };

__device__ __forceinline__ void mma_tile_step(const unsigned (*As)[PAD],
                                              const unsigned (*Bs)[PAD],
                                              int wm, int wn, int lane, MmaAcc& A)
{
    const int qr = lane >> 2;
    const int qc = lane & 3;
    #pragma unroll
    for (int kt = 0; kt < 2; kt++) {
        const int kb = kt * 8;
        unsigned a[2][4];
        #pragma unroll
        for (int mi = 0; mi < 2; mi++) {
            const int rb = wm + mi * 16 + qr;
            a[mi][0] = As[rb    ][kb + qc];
            a[mi][1] = As[rb + 8][kb + qc];
            a[mi][2] = As[rb    ][kb + qc + 4];
            a[mi][3] = As[rb + 8][kb + qc + 4];
        }
        unsigned b[4][2];
        #pragma unroll
        for (int ni = 0; ni < 4; ni++) {
            const int nb = wn + ni * 8 + qr;
            b[ni][0] = Bs[nb][kb + qc];
            b[ni][1] = Bs[nb][kb + qc + 4];
        }
        #pragma unroll
        for (int mi = 0; mi < 2; mi++)
            #pragma unroll
            for (int ni = 0; ni < 4; ni++)
                mma_tf32(A.c[mi][ni][0], A.c[mi][ni][1], A.c[mi][ni][2], A.c[mi][ni][3],
                         a[mi][0], a[mi][1], a[mi][2], a[mi][3], b[ni][0], b[ni][1]);
    }
}

// ---------------------------------------------------------------------------
// Batched tap conv (tf32 MMA + v4 RED scatter)
// ---------------------------------------------------------------------------
__global__ __launch_bounds__(256) void conv_taps(
    const float* __restrict__ X, const float* __restrict__ W27,
    float* __restrict__ C, const int* __restrict__ maps,
    int Mpad, int n, int cin, int cout)
{
    __shared__ unsigned As[128][PAD];
    __shared__ unsigned Bs[64][PAD];
    __shared__ float Cs[8][16][CPAD];
    __shared__ int gidx[128];
    __shared__ int sidx[128];

    const int z    = blockIdx.z;
    const int Mz   = (z == 26) ? n : Mpad;
    const int row0 = blockIdx.y * 128;
    if (row0 >= Mz) return;

    const int tap  = (z == 26) ? 13 : ((z < 13) ? z : z + 1);
    const float* W = W27 + (size_t)tap * cin * cout;
    const int col0 = blockIdx.x * 64;
    const int tid  = threadIdx.x;
    const int scrap = n;

    int myvalid = 0;
    if (tid < 128) {
        int r = row0 + tid;
        int g = -1, s = -1;
        if (r < Mz) {
            if (z == 26) { g = r; s = r; }
            else {
                g = maps[(size_t)z * Mpad + r];
                s = maps[(size_t)(26 + z) * Mpad + r];
            }
        }
        gidx[tid] = g;
        sidx[tid] = s;
        myvalid = (s >= 0 && s != scrap);
    }
    if (__syncthreads_count(myvalid) == 0) return;

    const int lane = tid & 31;
    const int warp = tid >> 5;
    const int wm = (warp & 3) * 32;
    const int wn = (warp >> 2) * 32;

    // A-load indexing (constant across k): thread covers row am, float4 slot aq
    const int am0 = tid >> 2, aq0 = tid & 3;
    const int am1 = (tid + 256) >> 2, aq1 = (tid + 256) & 3;
    // B-load indexing
    const int bn_[4] = { tid & 63, (tid + 256) & 63, (tid + 512) & 63, (tid + 768) & 63 };
    const int bk_[4] = { tid >> 6, (tid + 256) >> 6, (tid + 512) >> 6, (tid + 768) >> 6 };

    MmaAcc A;
    #pragma unroll
    for (int mi = 0; mi < 2; mi++)
        #pragma unroll
        for (int ni = 0; ni < 4; ni++)
            #pragma unroll
            for (int j = 0; j < 4; j++) A.c[mi][ni][j] = 0.f;

    float4 av0, av1; float bv[4];
    const int g0 = gidx[am0], g1 = gidx[am1];

    // prologue: load k0 = 0
    av0 = (g0 >= 0) ? *(const float4*)(X + (size_t)g0 * cin + aq0 * 4) : make_float4(0,0,0,0);
    av1 = (g1 >= 0) ? *(const float4*)(X + (size_t)g1 * cin + aq1 * 4) : make_float4(0,0,0,0);
    #pragma unroll
    for (int l = 0; l < 4; l++) bv[l] = W[(size_t)bk_[l] * cout + col0 + bn_[l]];

    for (int k0 = 0;; k0 += 16) {
        // store current regs to smem (converted)
        As[am0][aq0*4+0] = f2tf32(av0.x); As[am0][aq0*4+1] = f2tf32(av0.y);
        As[am0][aq0*4+2] = f2tf32(av0.z); As[am0][aq0*4+3] = f2tf32(av0.w);
        As[am1][aq1*4+0] = f2tf32(av1.x); As[am1][aq1*4+1] = f2tf32(av1.y);
        As[am1][aq1*4+2] = f2tf32(av1.z); As[am1][aq1*4+3] = f2tf32(av1.w);
        #pragma unroll
        for (int l = 0; l < 4; l++) Bs[bn_[l]][bk_[l]] = f2tf32(bv[l]);
        __syncthreads();

        if (k0 + 16 < cin) {
            // prefetch next tile into registers (overlaps with mma below)
            int kn = k0 + 16;
            av0 = (g0 >= 0) ? *(const float4*)(X + (size_t)g0 * cin + kn + aq0 * 4) : make_float4(0,0,0,0);
            av1 = (g1 >= 0) ? *(const float4*)(X + (size_t)g1 * cin + kn + aq1 * 4) : make_float4(0,0,0,0);
            #pragma unroll
            for (int l = 0; l < 4; l++) bv[l] = W[(size_t)(kn + bk_[l]) * cout + col0 + bn_[l]];
            mma_tile_step(As, Bs, wm, wn, lane, A);
            __syncthreads();
        } else {
            mma_tile_step(As, Bs, wm, wn, lane, A);
            break;
        }
    }

    // epilogue: stage 16 rows per warp through smem, v4 RED scatter
    const int qr = lane >> 2, qc = lane & 3;
    const int rr = lane >> 1;
    const int ch = (lane & 1) * 16;
    #pragma unroll
    for (int mi = 0; mi < 2; mi++) {
        #pragma unroll
        for (int ni = 0; ni < 4; ni++) {
            #pragma unroll
            for (int half = 0; half < 2; half++) {
                Cs[warp][qr + half*8][ni*8 + qc*2]     = A.c[mi][ni][half*2+0];
                Cs[warp][qr + half*8][ni*8 + qc*2 + 1] = A.c[mi][ni][half*2+1];
            }
        }
        __syncwarp();
        int o = sidx[wm + mi*16 + rr];
        if (o >= 0 && o != scrap) {
            float* cp = C + (size_t)o * cout + col0 + wn + ch;
            #pragma unroll
            for (int v = 0; v < 4; v++)
                red_add_v4(cp + v*4, *(const float4*)&Cs[warp][rr][ch + v*4]);
        }
        __syncwarp();
    }
}

// ---------------------------------------------------------------------------
// Batched transpose conv (tf32 MMA + v4 stores)
// ---------------------------------------------------------------------------
__global__ __launch_bounds__(256) void tconv8(
    const float* __restrict__ X, const float* __restrict__ W8,
    float* __restrict__ T, int n, int cin, int cout)
{
    __shared__ unsigned As[128][PAD];
    __shared__ unsigned Bs[64][PAD];
    __shared__ float Cs[8][16][CPAD];

    const int z    = blockIdx.z;
    const int row0 = blockIdx.y * 128;
    if (row0 >= n) return;
    const float* W = W8 + (size_t)z * cin * cout;
    const int col0 = blockIdx.x * 64;
    const int tid  = threadIdx.x;

    const int lane = tid & 31;
    const int warp = tid >> 5;
    const int wm = (warp & 3) * 32;
    const int wn = (warp >> 2) * 32;

    const int am0 = tid >> 2, aq0 = tid & 3;
    const int am1 = (tid + 256) >> 2, aq1 = (tid + 256) & 3;
    const int bn_[4] = { tid & 63, (tid + 256) & 63, (tid + 512) & 63, (tid + 768) & 63 };
    const int bk_[4] = { tid >> 6, (tid + 256) >> 6, (tid + 512) >> 6, (tid + 768) >> 6 };

    const int r0g = row0 + am0, r1g = row0 + am1;
    const long long p0 = (r0g < n) ? (long long)r0g * cin : -1;
    const long long p1 = (r1g < n) ? (long long)r1g * cin : -1;

    MmaAcc A;
    #pragma unroll
    for (int mi = 0; mi < 2; mi++)
        #pragma unroll
        for (int ni = 0; ni < 4; ni++)
            #pragma unroll
            for (int j = 0; j < 4; j++) A.c[mi][ni][j] = 0.f;

    float4 av0, av1; float bv[4];
    av0 = (p0 >= 0) ? *(const float4*)(X + p0 + aq0 * 4) : make_float4(0,0,0,0);
    av1 = (p1 >= 0) ? *(const float4*)(X + p1 + aq1 * 4) : make_float4(0,0,0,0);
    #pragma unroll
    for (int l = 0; l < 4; l++) bv[l] = W[(size_t)bk_[l] * cout + col0 + bn_[l]];

    for (int k0 = 0;; k0 += 16) {
        As[am0][aq0*4+0] = f2tf32(av0.x); As[am0][aq0*4+1] = f2tf32(av0.y);
        As[am0][aq0*4+2] = f2tf32(av0.z); As[am0][aq0*4+3] = f2tf32(av0.w);
        As[am1][aq1*4+0] = f2tf32(av1.x); As[am1][aq1*4+1] = f2tf32(av1.y);
        As[am1][aq1*4+2] = f2tf32(av1.z); As[am1][aq1*4+3] = f2tf32(av1.w);
        #pragma unroll
        for (int l = 0; l < 4; l++) Bs[bn_[l]][bk_[l]] = f2tf32(bv[l]);
        __syncthreads();

        if (k0 + 16 < cin) {
            int kn = k0 + 16;
            av0 = (p0 >= 0) ? *(const float4*)(X + p0 + kn + aq0 * 4) : make_float4(0,0,0,0);
            av1 = (p1 >= 0) ? *(const float4*)(X + p1 + kn + aq1 * 4) : make_float4(0,0,0,0);
            #pragma unroll
            for (int l = 0; l < 4; l++) bv[l] = W[(size_t)(kn + bk_[l]) * cout + col0 + bn_[l]];
            mma_tile_step(As, Bs, wm, wn, lane, A);
            __syncthreads();
        } else {
            mma_tile_step(As, Bs, wm, wn, lane, A);
            break;
        }
    }

    const int qr = lane >> 2, qc = lane & 3;
    const int rr = lane >> 1;
    const int ch = (lane & 1) * 16;
    #pragma unroll
    for (int mi = 0; mi < 2; mi++) {
        #pragma unroll
        for (int ni = 0; ni < 4; ni++) {
            #pragma unroll
            for (int half = 0; half < 2; half++) {
                Cs[warp][qr + half*8][ni*8 + qc*2]     = A.c[mi][ni][half*2+0];
                Cs[warp][qr + half*8][ni*8 + qc*2 + 1] = A.c[mi][ni][half*2+1];
            }
        }
        __syncwarp();
        int r = row0 + wm + mi*16 + rr;
        if (r < n) {
            float* tp = T + ((size_t)z * n + r) * cout + col0 + wn + ch;
            #pragma unroll
            for (int v = 0; v < 4; v++)
                *(float4*)(tp + v*4) = *(const float4*)&Cs[warp][rr][ch + v*4];
        }
        __syncwarp();
    }
}

// ---------------------------------------------------------------------------
// BatchNorm (training-mode batch stats) + ELU
// ---------------------------------------------------------------------------
__global__ void bn_stats(const float* __restrict__ X, int n, int c,
                         float* __restrict__ stats)
{
    int ch = threadIdx.x;
    int r0 = blockIdx.x * 128;
    int rend = r0 + 128; if (rend > n) rend = n;
    float s = 0.f, sq = 0.f;
    for (int r = r0; r < rend; r++) {
        float v = X[(size_t)r * c + ch];
        s += v; sq += v * v;
    }
    atomicAdd(&stats[ch], s);
    atomicAdd(&stats[c + ch], sq);
}

__global__ void bn_apply(const float* __restrict__ X, float* __restrict__ Y,
                         const float* __restrict__ stats,
                         const float* __restrict__ gb, long long total, int n, int c)
{
    long long i = (long long)blockIdx.x * blockDim.x + threadIdx.x;
    if (i >= total) return;
    int ch = (int)(i % c);
    float inv_n = 1.f / (float)n;
    float mu  = stats[ch] * inv_n;
    float var = stats[c + ch] * inv_n - mu * mu;
    float v = gb[ch] * (X[i] - mu) * rsqrtf(var + 1e-5f) + gb[c + ch];
    Y[i] = (v > 0.f) ? v : expm1f(v);
}

// ---------------------------------------------------------------------------
// Sparse-add scatter helpers
// ---------------------------------------------------------------------------
__global__ void scatter_copy(const float* __restrict__ src, float* __restrict__ dst,
                             const int* __restrict__ idx, long long total, int c)
{
    long long i = (long long)blockIdx.x * blockDim.x + threadIdx.x;
    if (i >= total) return;
    int r = (int)(i / c), ch = (int)(i % c);
    dst[(size_t)idx[r] * c + ch] = src[i];
}

__global__ void scatter_add(const float* __restrict__ src, float* __restrict__ dst,
                            const int* __restrict__ idx, long long total, int c)
{
    long long i = (long long)blockIdx.x * blockDim.x + threadIdx.x;
    if (i >= total) return;
    int r = (int)(i / c), ch = (int)(i % c);
    dst[(size_t)idx[r] * c + ch] += src[i];
}

// ---------------------------------------------------------------------------
// Host-side orchestration
// ---------------------------------------------------------------------------
static void sconv3_launch(const float* X, const float* W, const int* m,
                          int n, int Mpad, int cin, int cout, float* acc)
{
    dim3 grid(cout / 64, (n + 127) / 128, 27);
    conv_taps<<<grid, 256>>>(X, W, acc, m, Mpad, n, cin, cout);
}

static void bn_elu_launch(const float* X, float* Y, const float* gb,
                          int n, int c, float* stats)
{
    cudaMemsetAsync(stats, 0, 2 * c * sizeof(float), 0);
    bn_stats<<<(n + 127) / 128, c>>>(X, n, c, stats);
    long long total = (long long)n * c;
    bn_apply<<<(unsigned)((total + 255) / 256), 256>>>(X, Y, stats, gb, total, n, c);
}

extern "C" void kernel_launch(void* const* d_in, const int* in_sizes, int n_in,
                              void* d_out, int out_size)
{
    const float* feats0 = (const float*)d_in[0];
    const float* feats1 = (const float*)d_in[1];
    const float* feats2 = (const float*)d_in[2];
    const float* w_out0 = (const float*)d_in[3];
    const float* w_out1 = (const float*)d_in[4];
    const float* w_out2 = (const float*)d_in[5];
    const float* wt2    = (const float*)d_in[6];
    const float* wu2    = (const float*)d_in[7];
    const float* wt1    = (const float*)d_in[8];
    const float* wu1    = (const float*)d_in[9];
    const float* bn_out0 = (const float*)d_in[10];
    const float* bn_out1 = (const float*)d_in[11];
    const float* bn_out2 = (const float*)d_in[12];
    const float* bn_up2a = (const float*)d_in[13];
    const float* bn_up2b = (const float*)d_in[14];
    const float* bn_up1a = (const float*)d_in[15];
    const float* bn_up1b = (const float*)d_in[16];
    const int* m_c2 = (const int*)d_in[19];
    const int* m_g2 = (const int*)d_in[20];
    const int* m_u1 = (const int*)d_in[21];
    const int* m_g1 = (const int*)d_in[22];
    const int* m_u0 = (const int*)d_in[23];
    const int* lat1_idx = (const int*)d_in[24];
    const int* up1_idx  = (const int*)d_in[25];
    const int* lat0_idx = (const int*)d_in[26];
    const int* up0_idx  = (const int*)d_in[27];

    const int N0 = in_sizes[0] / 64;
    const int N1 = in_sizes[1] / 128;
    const int N2 = in_sizes[2] / 256;
    const int U1 = in_sizes[17] / 128;
    const int U0 = in_sizes[18] / 64;
    const int Mc2 = in_sizes[19] / 52;
    const int Mg2 = in_sizes[20] / 52;
    const int Mu1 = in_sizes[21] / 52;
    const int Mg1 = in_sizes[22] / 52;
    const int Mu0 = in_sizes[23] / 52;
    const int G2 = 8 * N2;
    const int G1 = 8 * U1;

    float *acc2, *tg2, *accg2, *x1, *acc1, *t1, *accg1, *x0, *acc0, *stats;
    cudaGetSymbolAddress((void**)&acc2,  g_acc2);
    cudaGetSymbolAddress((void**)&tg2,   g_tg2);
    cudaGetSymbolAddress((void**)&accg2, g_accg2);
    cudaGetSymbolAddress((void**)&x1,    g_x1);
    cudaGetSymbolAddress((void**)&acc1,  g_acc1);
    cudaGetSymbolAddress((void**)&t1,    g_t1);
    cudaGetSymbolAddress((void**)&accg1, g_accg1);
    cudaGetSymbolAddress((void**)&x0,    g_x0);
    cudaGetSymbolAddress((void**)&acc0,  g_acc0);
    cudaGetSymbolAddress((void**)&stats, g_stats);

    float* out0 = (float*)d_out;
    float* out1 = out0 + (size_t)U0 * 128;
    float* out2 = out1 + (size_t)U1 * 128;

    // ===== level 2 =====
    cudaMemsetAsync(acc2, 0, (size_t)(N2 + 1) * 128 * sizeof(float), 0);
    sconv3_launch(feats2, w_out2, m_c2, N2, Mc2, 256, 128, acc2);
    bn_elu_launch(acc2, out2, bn_out2, N2, 128, stats);

    // ===== up block 2 =====
    {
        dim3 grid(128 / 64, (N2 + 127) / 128, 8);
        tconv8<<<grid, 256>>>(feats2, wt2, tg2, N2, 256, 128);
    }
    bn_elu_launch(tg2, tg2, bn_up2a, G2, 128, stats);
    cudaMemsetAsync(accg2, 0, (size_t)(G2 + 1) * 128 * sizeof(float), 0);
    sconv3_launch(tg2, wu2, m_g2, G2, Mg2, 128, 128, accg2);
    bn_elu_launch(accg2, accg2, bn_up2b, G2, 128, stats);

    // ===== x1 = union add =====
    cudaMemsetAsync(x1, 0, (size_t)U1 * 128 * sizeof(float), 0);
    {
        long long t = (long long)N1 * 128;
        scatter_copy<<<(unsigned)((t + 255) / 256), 256>>>(feats1, x1, lat1_idx, t, 128);
        t = (long long)G2 * 128;
        scatter_add<<<(unsigned)((t + 255) / 256), 256>>>(accg2, x1, up1_idx, t, 128);
    }

    // ===== out1 =====
    cudaMemsetAsync(acc1, 0, (size_t)(U1 + 1) * 128 * sizeof(float), 0);
    sconv3_launch(x1, w_out1, m_u1, U1, Mu1, 128, 128, acc1);
    bn_elu_launch(acc1, out1, bn_out1, U1, 128, stats);

    // ===== up block 1 =====
    {
        dim3 grid(64 / 64, (U1 + 127) / 128, 8);
        tconv8<<<grid, 256>>>(x1, wt1, t1, U1, 128, 64);
    }
    bn_elu_launch(t1, t1, bn_up1a, G1, 64, stats);
    cudaMemsetAsync(accg1, 0, (size_t)(G1 + 1) * 64 * sizeof(float), 0);
    sconv3_launch(t1, wu1, m_g1, G1, Mg1, 64, 64, accg1);
    bn_elu_launch(accg1, accg1, bn_up1b, G1, 64, stats);

    // ===== x0 = union add =====
    cudaMemsetAsync(x0, 0, (size_t)U0 * 64 * sizeof(float), 0);
    {
        long long t = (long long)N0 * 64;
        scatter_copy<<<(unsigned)((t + 255) / 256), 256>>>(feats0, x0, lat0_idx, t, 64);
        t = (long long)G1 * 64;
        scatter_add<<<(unsigned)((t + 255) / 256), 256>>>(accg1, x0, up0_idx, t, 64);
    }

    // ===== out0 =====
    cudaMemsetAsync(acc0, 0, (size_t)(U0 + 1) * 128 * sizeof(float), 0);
    sconv3_launch(x0, w_out0, m_u0, U0, Mu0, 64, 128, acc0);
    bn_elu_launch(acc0, out0, bn_out0, U0, 128, stats);
}

// round 5
// speedup vs baseline: 10.3528x; 1.2022x over previous
#include <cuda_runtime.h>
#include <math.h>

// ---------------------------------------------------------------------------
// Static scratch (allocation-free per harness rules)
// ---------------------------------------------------------------------------
#define N2MAX 1536
#define G2MAX (8*N2MAX)
#define U1MAX 15872
#define G1MAX (8*U1MAX)
#define U0MAX 160256

__device__ float g_acc2[(N2MAX+1)*128];
__device__ float g_tg2[(size_t)G2MAX*128];
__device__ float g_accg2[((size_t)G2MAX+1)*128];
__device__ float g_x1[(size_t)U1MAX*128];
__device__ float g_acc1[((size_t)U1MAX+1)*128];
__device__ float g_t1[(size_t)G1MAX*64];
__device__ float g_accg1[((size_t)G1MAX+1)*64];
__device__ float g_x0[(size_t)U0MAX*64];
__device__ float g_acc0[((size_t)U0MAX+1)*128];
__device__ float g_stats[256];

#define PAD 20   // smem row stride (words): conflict-free mma fragment LDS

__device__ __forceinline__ unsigned f2tf32(float f) {
    unsigned r;
    asm("cvt.rna.tf32.f32 %0, %1;" : "=r"(r) : "f"(f));
    return r;
}

__device__ __forceinline__ void mma_tf32(float& c0, float& c1, float& c2, float& c3,
                                         unsigned a0, unsigned a1, unsigned a2, unsigned a3,
                                         unsigned b0, unsigned b1)
{
    asm volatile("mma.sync.aligned.m16n8k8.row.col.f32.tf32.tf32.f32 "
                 "{%0,%1,%2,%3},{%4,%5,%6,%7},{%8,%9},{%0,%1,%2,%3};"
                 : "+f"(c0), "+f"(c1), "+f"(c2), "+f"(c3)
                 : "r"(a0), "r"(a1), "r"(a2), "r"(a3), "r"(b0), "r"(b1));
}

__device__ __forceinline__ void red_add_v2(float* p, float a, float b) {
    asm volatile("red.global.add.v2.f32 [%0], {%1,%2};"
                 :: "l"(p), "f"(a), "f"(b) : "memory");
}

// ---------------------------------------------------------------------------
// Warp MMA step over one 128 x TN smem tile slice (k = 16).
// Warps: 4(m) x 2(n). Warp tile: 32 x TN/2. NI = TN/16 n8-tiles per warp.
// ---------------------------------------------------------------------------
template<int NI>
__device__ __forceinline__ void mma_step(const unsigned (*As)[PAD],
                                         const unsigned (*Bs)[PAD],
                                         int wm, int wn, int lane,
                                         float (&c)[2][NI][4])
{
    const int qr = lane >> 2;
    const int qc = lane & 3;
    #pragma unroll
    for (int kt = 0; kt < 2; kt++) {
        const int kb = kt * 8;
        unsigned a[2][4];
        #pragma unroll
        for (int mi = 0; mi < 2; mi++) {
            const int rb = wm + mi * 16 + qr;
            a[mi][0] = As[rb    ][kb + qc];
            a[mi][1] = As[rb + 8][kb + qc];
            a[mi][2] = As[rb    ][kb + qc + 4];
            a[mi][3] = As[rb + 8][kb + qc + 4];
        }
        unsigned b[NI][2];
        #pragma unroll
        for (int ni = 0; ni < NI; ni++) {
            const int nb = wn + ni * 8 + qr;
            b[ni][0] = Bs[nb][kb + qc];
            b[ni][1] = Bs[nb][kb + qc + 4];
        }
        #pragma unroll
        for (int mi = 0; mi < 2; mi++)
            #pragma unroll
            for (int ni = 0; ni < NI; ni++)
                mma_tf32(c[mi][ni][0], c[mi][ni][1], c[mi][ni][2], c[mi][ni][3],
                         a[mi][0], a[mi][1], a[mi][2], a[mi][3], b[ni][0], b[ni][1]);
    }
}

// ---------------------------------------------------------------------------
// Batched tap conv (tf32 MMA, TN = cout, double-buffered, 1 sync/k-step)
// grid = (ceil(n/128), 27)
// ---------------------------------------------------------------------------
template<int TN>
__global__ __launch_bounds__(256, 2) void conv_taps_t(
    const float* __restrict__ X, const float* __restrict__ W27,
    float* __restrict__ C, const int* __restrict__ maps,
    int Mpad, int n, int cin)
{
    constexpr int cout = TN;
    constexpr int NI = TN / 16;
    constexpr int BL = TN / 16;      // B elems per thread per k-step
    constexpr int KS = 256 / TN;     // B k-stride between elems

    __shared__ unsigned As[2][128][PAD];
    __shared__ unsigned Bs[2][TN][PAD];
    __shared__ int gidx[128], sidx[128];

    const int z    = blockIdx.y;
    const int Mz   = (z == 26) ? n : Mpad;
    const int row0 = blockIdx.x * 128;
    if (row0 >= Mz) return;

    const int tap  = (z == 26) ? 13 : ((z < 13) ? z : z + 1);
    const float* W = W27 + (size_t)tap * cin * cout;
    const int tid  = threadIdx.x;
    const int scrap = n;

    int myvalid = 0;
    if (tid < 128) {
        int r = row0 + tid;
        int g = -1, s = -1;
        if (r < Mz) {
            if (z == 26) { g = r; s = r; }
            else {
                g = maps[(size_t)z * Mpad + r];
                s = maps[(size_t)(26 + z) * Mpad + r];
            }
        }
        gidx[tid] = g;
        sidx[tid] = s;
        myvalid = (s >= 0 && s != scrap);
    }
    if (__syncthreads_count(myvalid) == 0) return;

    const int lane = tid & 31;
    const int warp = tid >> 5;
    const int wm = (warp & 3) * 32;
    const int wn = (warp >> 2) * (TN / 2);

    const int am0 = tid >> 2, am1 = am0 + 64;
    const int aq  = (tid & 3) * 4;
    const int bn  = tid & (TN - 1);
    const int bk0 = tid / TN;

    float c[2][NI][4];
    #pragma unroll
    for (int mi = 0; mi < 2; mi++)
        #pragma unroll
        for (int ni = 0; ni < NI; ni++)
            #pragma unroll
            for (int j = 0; j < 4; j++) c[mi][ni][j] = 0.f;

    const int g0 = gidx[am0], g1 = gidx[am1];
    float4 av0, av1; float bv[BL];

    // prologue load k0 = 0
    av0 = (g0 >= 0) ? *(const float4*)(X + (size_t)g0 * cin + aq) : make_float4(0,0,0,0);
    av1 = (g1 >= 0) ? *(const float4*)(X + (size_t)g1 * cin + aq) : make_float4(0,0,0,0);
    #pragma unroll
    for (int l = 0; l < BL; l++)
        bv[l] = W[(size_t)(bk0 + l * KS) * cout + bn];
    // store to buffer 0
    As[0][am0][aq+0] = f2tf32(av0.x); As[0][am0][aq+1] = f2tf32(av0.y);
    As[0][am0][aq+2] = f2tf32(av0.z); As[0][am0][aq+3] = f2tf32(av0.w);
    As[0][am1][aq+0] = f2tf32(av1.x); As[0][am1][aq+1] = f2tf32(av1.y);
    As[0][am1][aq+2] = f2tf32(av1.z); As[0][am1][aq+3] = f2tf32(av1.w);
    #pragma unroll
    for (int l = 0; l < BL; l++) Bs[0][bn][bk0 + l * KS] = f2tf32(bv[l]);
    __syncthreads();

    int buf = 0;
    for (int k0 = 0;; k0 += 16) {
        const bool more = (k0 + 16 < cin);
        if (more) {
            const int kn = k0 + 16;
            av0 = (g0 >= 0) ? *(const float4*)(X + (size_t)g0 * cin + kn + aq) : make_float4(0,0,0,0);
            av1 = (g1 >= 0) ? *(const float4*)(X + (size_t)g1 * cin + kn + aq) : make_float4(0,0,0,0);
            #pragma unroll
            for (int l = 0; l < BL; l++)
                bv[l] = W[(size_t)(kn + bk0 + l * KS) * cout + bn];
        }
        mma_step<NI>(As[buf], Bs[buf], wm, wn, lane, c);
        if (!more) break;
        const int nb2 = buf ^ 1;
        As[nb2][am0][aq+0] = f2tf32(av0.x); As[nb2][am0][aq+1] = f2tf32(av0.y);
        As[nb2][am0][aq+2] = f2tf32(av0.z); As[nb2][am0][aq+3] = f2tf32(av0.w);
        As[nb2][am1][aq+0] = f2tf32(av1.x); As[nb2][am1][aq+1] = f2tf32(av1.y);
        As[nb2][am1][aq+2] = f2tf32(av1.z); As[nb2][am1][aq+3] = f2tf32(av1.w);
        #pragma unroll
        for (int l = 0; l < BL; l++) Bs[nb2][bn][bk0 + l * KS] = f2tf32(bv[l]);
        __syncthreads();
        buf = nb2;
    }

    // epilogue: v2 RED scatter
    const int qr = lane >> 2, qc = lane & 3;
    #pragma unroll
    for (int mi = 0; mi < 2; mi++) {
        #pragma unroll
        for (int half = 0; half < 2; half++) {
            const int lr = wm + mi * 16 + qr + half * 8;
            const int o = sidx[lr];
            if (o < 0 || o == scrap) continue;
            float* cp = C + (size_t)o * cout + wn + qc * 2;
            #pragma unroll
            for (int ni = 0; ni < NI; ni++)
                red_add_v2(cp + ni * 8, c[mi][ni][half*2], c[mi][ni][half*2+1]);
        }
    }
}

// ---------------------------------------------------------------------------
// Batched transpose conv (tf32 MMA, TN = cout): T[z*n + r] = X[r] @ Wt[z]
// grid = (ceil(n/128), 8)
// ---------------------------------------------------------------------------
template<int TN>
__global__ __launch_bounds__(256, 2) void tconv8_t(
    const float* __restrict__ X, const float* __restrict__ W8,
    float* __restrict__ T, int n, int cin)
{
    constexpr int cout = TN;
    constexpr int NI = TN / 16;
    constexpr int BL = TN / 16;
    constexpr int KS = 256 / TN;

    __shared__ unsigned As[2][128][PAD];
    __shared__ unsigned Bs[2][TN][PAD];

    const int z    = blockIdx.y;
    const int row0 = blockIdx.x * 128;
    if (row0 >= n) return;
    const float* W = W8 + (size_t)z * cin * cout;
    const int tid  = threadIdx.x;

    const int lane = tid & 31;
    const int warp = tid >> 5;
    const int wm = (warp & 3) * 32;
    const int wn = (warp >> 2) * (TN / 2);

    const int am0 = tid >> 2, am1 = am0 + 64;
    const int aq  = (tid & 3) * 4;
    const int bn  = tid & (TN - 1);
    const int bk0 = tid / TN;

    const int r0g = row0 + am0, r1g = row0 + am1;
    const long long p0 = (r0g < n) ? (long long)r0g * cin : -1;
    const long long p1 = (r1g < n) ? (long long)r1g * cin : -1;

    float c[2][NI][4];
    #pragma unroll
    for (int mi = 0; mi < 2; mi++)
        #pragma unroll
        for (int ni = 0; ni < NI; ni++)
            #pragma unroll
            for (int j = 0; j < 4; j++) c[mi][ni][j] = 0.f;

    float4 av0, av1; float bv[BL];
    av0 = (p0 >= 0) ? *(const float4*)(X + p0 + aq) : make_float4(0,0,0,0);
    av1 = (p1 >= 0) ? *(const float4*)(X + p1 + aq) : make_float4(0,0,0,0);
    #pragma unroll
    for (int l = 0; l < BL; l++)
        bv[l] = W[(size_t)(bk0 + l * KS) * cout + bn];
    As[0][am0][aq+0] = f2tf32(av0.x); As[0][am0][aq+1] = f2tf32(av0.y);
    As[0][am0][aq+2] = f2tf32(av0.z); As[0][am0][aq+3] = f2tf32(av0.w);
    As[0][am1][aq+0] = f2tf32(av1.x); As[0][am1][aq+1] = f2tf32(av1.y);
    As[0][am1][aq+2] = f2tf32(av1.z); As[0][am1][aq+3] = f2tf32(av1.w);
    #pragma unroll
    for (int l = 0; l < BL; l++) Bs[0][bn][bk0 + l * KS] = f2tf32(bv[l]);
    __syncthreads();

    int buf = 0;
    for (int k0 = 0;; k0 += 16) {
        const bool more = (k0 + 16 < cin);
        if (more) {
            const int kn = k0 + 16;
            av0 = (p0 >= 0) ? *(const float4*)(X + p0 + kn + aq) : make_float4(0,0,0,0);
            av1 = (p1 >= 0) ? *(const float4*)(X + p1 + kn + aq) : make_float4(0,0,0,0);
            #pragma unroll
            for (int l = 0; l < BL; l++)
                bv[l] = W[(size_t)(kn + bk0 + l * KS) * cout + bn];
        }
        mma_step<NI>(As[buf], Bs[buf], wm, wn, lane, c);
        if (!more) break;
        const int nb2 = buf ^ 1;
        As[nb2][am0][aq+0] = f2tf32(av0.x); As[nb2][am0][aq+1] = f2tf32(av0.y);
        As[nb2][am0][aq+2] = f2tf32(av0.z); As[nb2][am0][aq+3] = f2tf32(av0.w);
        As[nb2][am1][aq+0] = f2tf32(av1.x); As[nb2][am1][aq+1] = f2tf32(av1.y);
        As[nb2][am1][aq+2] = f2tf32(av1.z); As[nb2][am1][aq+3] = f2tf32(av1.w);
        #pragma unroll
        for (int l = 0; l < BL; l++) Bs[nb2][bn][bk0 + l * KS] = f2tf32(bv[l]);
        __syncthreads();
        buf = nb2;
    }

    const int qr = lane >> 2, qc = lane & 3;
    #pragma unroll
    for (int mi = 0; mi < 2; mi++) {
        #pragma unroll
        for (int half = 0; half < 2; half++) {
            const int r = row0 + wm + mi * 16 + qr + half * 8;
            if (r >= n) continue;
            float* tp = T + ((size_t)z * n + r) * cout + wn + qc * 2;
            #pragma unroll
            for (int ni = 0; ni < NI; ni++)
                *(float2*)(tp + ni * 8) = make_float2(c[mi][ni][half*2], c[mi][ni][half*2+1]);
        }
    }
}

// ---------------------------------------------------------------------------
// BatchNorm (training-mode batch stats) + ELU
// ---------------------------------------------------------------------------
__global__ void bn_stats(const float* __restrict__ X, int n, int c,
                         float* __restrict__ stats)
{
    int ch = threadIdx.x;
    int r0 = blockIdx.x * 128;
    int rend = r0 + 128; if (rend > n) rend = n;
    float s = 0.f, sq = 0.f;
    for (int r = r0; r < rend; r++) {
        float v = X[(size_t)r * c + ch];
        s += v; sq += v * v;
    }
    atomicAdd(&stats[ch], s);
    atomicAdd(&stats[c + ch], sq);
}

__global__ void bn_apply(const float* __restrict__ X, float* __restrict__ Y,
                         const float* __restrict__ stats,
                         const float* __restrict__ gb, long long total, int n, int c)
{
    long long i = (long long)blockIdx.x * blockDim.x + threadIdx.x;
    if (i >= total) return;
    int ch = (int)(i % c);
    float inv_n = 1.f / (float)n;
    float mu  = stats[ch] * inv_n;
    float var = stats[c + ch] * inv_n - mu * mu;
    float v = gb[ch] * (X[i] - mu) * rsqrtf(var + 1e-5f) + gb[c + ch];
    Y[i] = (v > 0.f) ? v : expm1f(v);
}

// ---------------------------------------------------------------------------
// Sparse-add scatter helpers
// ---------------------------------------------------------------------------
__global__ void scatter_copy(const float* __restrict__ src, float* __restrict__ dst,
                             const int* __restrict__ idx, long long total, int c)
{
    long long i = (long long)blockIdx.x * blockDim.x + threadIdx.x;
    if (i >= total) return;
    int r = (int)(i / c), ch = (int)(i % c);
    dst[(size_t)idx[r] * c + ch] = src[i];
}

__global__ void scatter_add(const float* __restrict__ src, float* __restrict__ dst,
                            const int* __restrict__ idx, long long total, int c)
{
    long long i = (long long)blockIdx.x * blockDim.x + threadIdx.x;
    if (i >= total) return;
    int r = (int)(i / c), ch = (int)(i % c);
    dst[(size_t)idx[r] * c + ch] += src[i];
}

// ---------------------------------------------------------------------------
// Host-side orchestration
// ---------------------------------------------------------------------------
static void sconv3_launch(const float* X, const float* W, const int* m,
                          int n, int Mpad, int cin, int cout, float* acc)
{
    dim3 grid((n + 127) / 128, 27);
    if (cout == 128)
        conv_taps_t<128><<<grid, 256>>>(X, W, acc, m, Mpad, n, cin);
    else
        conv_taps_t<64><<<grid, 256>>>(X, W, acc, m, Mpad, n, cin);
}

static void tconv_launch(const float* X, const float* W8, float* T,
                         int n, int cin, int cout)
{
    dim3 grid((n + 127) / 128, 8);
    if (cout == 128)
        tconv8_t<128><<<grid, 256>>>(X, W8, T, n, cin);
    else
        tconv8_t<64><<<grid, 256>>>(X, W8, T, n, cin);
}

static void bn_elu_launch(const float* X, float* Y, const float* gb,
                          int n, int c, float* stats)
{
    cudaMemsetAsync(stats, 0, 2 * c * sizeof(float), 0);
    bn_stats<<<(n + 127) / 128, c>>>(X, n, c, stats);
    long long total = (long long)n * c;
    bn_apply<<<(unsigned)((total + 255) / 256), 256>>>(X, Y, stats, gb, total, n, c);
}

extern "C" void kernel_launch(void* const* d_in, const int* in_sizes, int n_in,
                              void* d_out, int out_size)
{
    const float* feats0 = (const float*)d_in[0];
    const float* feats1 = (const float*)d_in[1];
    const float* feats2 = (const float*)d_in[2];
    const float* w_out0 = (const float*)d_in[3];
    const float* w_out1 = (const float*)d_in[4];
    const float* w_out2 = (const float*)d_in[5];
    const float* wt2    = (const float*)d_in[6];
    const float* wu2    = (const float*)d_in[7];
    const float* wt1    = (const float*)d_in[8];
    const float* wu1    = (const float*)d_in[9];
    const float* bn_out0 = (const float*)d_in[10];
    const float* bn_out1 = (const float*)d_in[11];
    const float* bn_out2 = (const float*)d_in[12];
    const float* bn_up2a = (const float*)d_in[13];
    const float* bn_up2b = (const float*)d_in[14];
    const float* bn_up1a = (const float*)d_in[15];
    const float* bn_up1b = (const float*)d_in[16];
    const int* m_c2 = (const int*)d_in[19];
    const int* m_g2 = (const int*)d_in[20];
    const int* m_u1 = (const int*)d_in[21];
    const int* m_g1 = (const int*)d_in[22];
    const int* m_u0 = (const int*)d_in[23];
    const int* lat1_idx = (const int*)d_in[24];
    const int* up1_idx  = (const int*)d_in[25];
    const int* lat0_idx = (const int*)d_in[26];
    const int* up0_idx  = (const int*)d_in[27];

    const int N0 = in_sizes[0] / 64;
    const int N1 = in_sizes[1] / 128;
    const int N2 = in_sizes[2] / 256;
    const int U1 = in_sizes[17] / 128;
    const int U0 = in_sizes[18] / 64;
    const int Mc2 = in_sizes[19] / 52;
    const int Mg2 = in_sizes[20] / 52;
    const int Mu1 = in_sizes[21] / 52;
    const int Mg1 = in_sizes[22] / 52;
    const int Mu0 = in_sizes[23] / 52;
    const int G2 = 8 * N2;
    const int G1 = 8 * U1;

    float *acc2, *tg2, *accg2, *x1, *acc1, *t1, *accg1, *x0, *acc0, *stats;
    cudaGetSymbolAddress((void**)&acc2,  g_acc2);
    cudaGetSymbolAddress((void**)&tg2,   g_tg2);
    cudaGetSymbolAddress((void**)&accg2, g_accg2);
    cudaGetSymbolAddress((void**)&x1,    g_x1);
    cudaGetSymbolAddress((void**)&acc1,  g_acc1);
    cudaGetSymbolAddress((void**)&t1,    g_t1);
    cudaGetSymbolAddress((void**)&accg1, g_accg1);
    cudaGetSymbolAddress((void**)&x0,    g_x0);
    cudaGetSymbolAddress((void**)&acc0,  g_acc0);
    cudaGetSymbolAddress((void**)&stats, g_stats);

    float* out0 = (float*)d_out;
    float* out1 = out0 + (size_t)U0 * 128;
    float* out2 = out1 + (size_t)U1 * 128;

    // ===== level 2 =====
    cudaMemsetAsync(acc2, 0, (size_t)(N2 + 1) * 128 * sizeof(float), 0);
    sconv3_launch(feats2, w_out2, m_c2, N2, Mc2, 256, 128, acc2);
    bn_elu_launch(acc2, out2, bn_out2, N2, 128, stats);

    // ===== up block 2 =====
    tconv_launch(feats2, wt2, tg2, N2, 256, 128);
    bn_elu_launch(tg2, tg2, bn_up2a, G2, 128, stats);
    cudaMemsetAsync(accg2, 0, (size_t)(G2 + 1) * 128 * sizeof(float), 0);
    sconv3_launch(tg2, wu2, m_g2, G2, Mg2, 128, 128, accg2);
    bn_elu_launch(accg2, accg2, bn_up2b, G2, 128, stats);

    // ===== x1 = union add =====
    cudaMemsetAsync(x1, 0, (size_t)U1 * 128 * sizeof(float), 0);
    {
        long long t = (long long)N1 * 128;
        scatter_copy<<<(unsigned)((t + 255) / 256), 256>>>(feats1, x1, lat1_idx, t, 128);
        t = (long long)G2 * 128;
        scatter_add<<<(unsigned)((t + 255) / 256), 256>>>(accg2, x1, up1_idx, t, 128);
    }

    // ===== out1 =====
    cudaMemsetAsync(acc1, 0, (size_t)(U1 + 1) * 128 * sizeof(float), 0);
    sconv3_launch(x1, w_out1, m_u1, U1, Mu1, 128, 128, acc1);
    bn_elu_launch(acc1, out1, bn_out1, U1, 128, stats);

    // ===== up block 1 =====
    tconv_launch(x1, wt1, t1, U1, 128, 64);
    bn_elu_launch(t1, t1, bn_up1a, G1, 64, stats);
    cudaMemsetAsync(accg1, 0, (size_t)(G1 + 1) * 64 * sizeof(float), 0);
    sconv3_launch(t1, wu1, m_g1, G1, Mg1, 64, 64, accg1);
    bn_elu_launch(accg1, accg1, bn_up1b, G1, 64, stats);

    // ===== x0 = union add =====
    cudaMemsetAsync(x0, 0, (size_t)U0 * 64 * sizeof(float), 0);
    {
        long long t = (long long)N0 * 64;
        scatter_copy<<<(unsigned)((t + 255) / 256), 256>>>(feats0, x0, lat0_idx, t, 64);
        t = (long long)G1 * 64;
        scatter_add<<<(unsigned)((t + 255) / 256), 256>>>(accg1, x0, up0_idx, t, 64);
    }

    // ===== out0 =====
    cudaMemsetAsync(acc0, 0, (size_t)(U0 + 1) * 128 * sizeof(float), 0);
    sconv3_launch(x0, w_out0, m_u0, U0, Mu0, 64, 128, acc0);
    bn_elu_launch(acc0, out0, bn_out0, U0, 128, stats);
}